// round 2
// baseline (speedup 1.0000x reference)
#include <cuda_runtime.h>
#include <cuda_fp16.h>
#include <cuda_bf16.h>
#include <cstdint>

// LUT-based fp16 SiLU: out = fp32( k[idx]*h + b[idx] ), h = fp16(x)
// idx = sign(1b) | level=exp field(5b) | mi=top-4 mantissa bits(4b),
// with subnormal -> lvl=1,mi=0 and NaN passthrough, matching the numpy ref.
//
// Table inputs are identified at runtime:
//  - b_table[0] == 0.0 exactly (b = f0 - 0.5*x0 = 0 on the first segment)
//  - k_table[0] == 0.5 exactly
// so a sniff kernel distinguishes k vs b and the staged dtype
// (fp16 / fp32-upcast / bf16) from the first 32-bit word.

__device__ int g_mode;  // bit0: tables swapped (tA is b); bits[2:1]: 0=f16,1=f32,2=bf16

__global__ void sniff_kernel(const unsigned* __restrict__ tA,
                             const unsigned* __restrict__ tB)
{
    unsigned wA = tA[0];
    unsigned wB = tB[0];
    int swap = (wA == 0u) ? 1 : 0;          // table whose word0 is 0 is b_table
    unsigned kw = swap ? wB : wA;           // first word of k_table
    int dt;
    if (kw == 0x3F000000u)            dt = 1;   // fp32(0.5)
    else if ((kw & 0xFFFFu) == 0x3F00u) dt = 2; // bf16(0.5) low half
    else                              dt = 0;   // fp16(0.5) = 0x3800 low half
    g_mode = swap | (dt << 1);
}

__global__ __launch_bounds__(256)
void lut_silu_kernel(const float4* __restrict__ x,
                     const void* __restrict__ tA,
                     const void* __restrict__ tB,
                     float4* __restrict__ out,
                     int n4)
{
    __shared__ __half2 lut[1024];

    int mode = g_mode;
    const void* kp = (mode & 1) ? tB : tA;
    const void* bp = (mode & 1) ? tA : tB;
    int dt = mode >> 1;

    // Preload interleaved (k,b) LUT: 1024 entries, 4 KB.
    for (int i = threadIdx.x; i < 1024; i += blockDim.x) {
        __half kh, bh;
        if (dt == 1) {            // staged as fp32 (exact round-trip of f16 values)
            kh = __float2half(((const float*)kp)[i]);
            bh = __float2half(((const float*)bp)[i]);
        } else if (dt == 2) {     // staged as bf16 (fallback)
            kh = __float2half(__bfloat162float(((const __nv_bfloat16*)kp)[i]));
            bh = __float2half(__bfloat162float(((const __nv_bfloat16*)bp)[i]));
        } else {                  // native fp16
            kh = ((const __half*)kp)[i];
            bh = ((const __half*)bp)[i];
        }
        lut[i] = __halves2half2(kh, bh);
    }
    __syncthreads();

    int idx = blockIdx.x * blockDim.x + threadIdx.x;
    if (idx >= n4) return;

    float4 v = x[idx];
    float in[4] = {v.x, v.y, v.z, v.w};
    float r[4];

#pragma unroll
    for (int j = 0; j < 4; j++) {
        __half h = __float2half(in[j]);          // RN, matches astype(float16)
        unsigned short u = __half_as_ushort(h);
        unsigned sign = (u >> 15) & 1u;
        unsigned ef   = (u >> 10) & 31u;
        unsigned man  = u & 1023u;

        bool subn = (ef == 0u) && (man != 0u);   // subnormal -> lvl=1, mi=0
        unsigned lvl = subn ? 1u : ef;
        unsigned mi  = subn ? 0u : (man >> 6);

        unsigned li = (sign << 9) | (lvl << 4) | mi;
        __half2 kb = lut[li];

        // two separately-rounded fp16 ops (NOT fused) to match jnp float16
        __half prod = __hmul(__low2half(kb), h);
        __half res  = __hadd(prod, __high2half(kb));
        float rf = __half2float(res);

        if (ef == 31u && man != 0u) rf = __int_as_float(0x7fc00000); // NaN in -> NaN out
        r[j] = rf;
    }

    out[idx] = make_float4(r[0], r[1], r[2], r[3]);
}

extern "C" void kernel_launch(void* const* d_in, const int* in_sizes, int n_in,
                              void* d_out, int out_size)
{
    // x is the (only) large input; the other two are the 1024-entry tables,
    // kept in their given relative order (sniff kernel sorts out k vs b).
    int xi = 0;
    for (int i = 1; i < n_in; i++)
        if (in_sizes[i] > in_sizes[xi]) xi = i;

    const void* tabs[2];
    int t = 0;
    for (int i = 0; i < n_in && t < 2; i++)
        if (i != xi) tabs[t++] = d_in[i];

    const float* x = (const float*)d_in[xi];
    float* out = (float*)d_out;

    int n  = in_sizes[xi];
    int n4 = n >> 2;   // 4*4096*4096 divisible by 4

    sniff_kernel<<<1, 1>>>((const unsigned*)tabs[0], (const unsigned*)tabs[1]);

    int threads = 256;
    int blocks  = (n4 + threads - 1) / threads;
    lut_silu_kernel<<<blocks, threads>>>(
        (const float4*)x, tabs[0], tabs[1], (float4*)out, n4);
}

// round 4
// speedup vs baseline: 1.4325x; 1.4325x over previous
#include <cuda_runtime.h>
#include <cuda_fp16.h>
#include <cuda_bf16.h>
#include <cstdint>
#include <cstring>

// LUT fp16 SiLU: out = fp32( k[li]*h + b[li] ), h = fp16(x), li = (bits(h)>>6)&0x3FF.
// Raw bit-field index is exact for ALL inputs:
//  - normals/zero/inf: (u>>6)&0x3FF == sign<<9 | lvl<<4 | mi by construction
//  - subnormals: land in lvl-0 entries, which equal the reference's (lvl=1,mi=0)
//    entry exactly (k=0.5, b=0 exactly in both, since silu's quadratic correction
//    is far below fp16 half-ulp at those magnitudes)
//  - NaN: lvl-31 table entries are NaN (inf-inf in table gen) -> NaN propagates
//    through k*x+b, matching the reference's explicit NaN mask.
// fp16 math: separate HMUL2 + HADD2 (two roundings/lane) to match jnp float16.

__device__ int g_mode;  // bit0: tables swapped (tA is b); bits[2:1]: 0=f16,1=f32,2=bf16

__global__ void sniff_kernel(const unsigned* __restrict__ tA,
                             const unsigned* __restrict__ tB)
{
    unsigned wA = tA[0];
    unsigned wB = tB[0];
    int swap = (wA == 0u) ? 1 : 0;            // b_table[0] == 0.0 exactly
    unsigned kw = swap ? wB : wA;             // first word of k_table (k[0] == 0.5)
    int dt;
    if (kw == 0x3F000000u)              dt = 1;  // fp32(0.5)
    else if ((kw & 0xFFFFu) == 0x3F00u) dt = 2;  // bf16(0.5) low half
    else                                dt = 0;  // fp16(0.5)=0x3800 low half
    g_mode = swap | (dt << 1);
}

__device__ __forceinline__ unsigned h2_to_u(__half2 h) {
    unsigned u;
    memcpy(&u, &h, 4);
    return u;
}
__device__ __forceinline__ __half2 u_to_h2(unsigned u) {
    __half2 h;
    memcpy(&h, &u, 4);
    return h;
}

__device__ __forceinline__ float4 proc4(float4 v, const __half2* lut)
{
    __half2 h01 = __floats2half2_rn(v.x, v.y);
    __half2 h23 = __floats2half2_rn(v.z, v.w);
    unsigned u01 = h2_to_u(h01);
    unsigned u23 = h2_to_u(h23);

    unsigned li0 = (u01 >> 6) & 0x3FFu;
    unsigned li1 =  u01 >> 22;
    unsigned li2 = (u23 >> 6) & 0x3FFu;
    unsigned li3 =  u23 >> 22;

    unsigned kb0 = h2_to_u(lut[li0]);
    unsigned kb1 = h2_to_u(lut[li1]);
    unsigned kb2 = h2_to_u(lut[li2]);
    unsigned kb3 = h2_to_u(lut[li3]);

    // (k0,b0),(k1,b1) -> (k0,k1),(b0,b1)
    __half2 k01 = u_to_h2(__byte_perm(kb0, kb1, 0x5410));
    __half2 b01 = u_to_h2(__byte_perm(kb0, kb1, 0x7632));
    __half2 k23 = u_to_h2(__byte_perm(kb2, kb3, 0x5410));
    __half2 b23 = u_to_h2(__byte_perm(kb2, kb3, 0x7632));

    __half2 r01 = __hadd2(__hmul2(k01, h01), b01);
    __half2 r23 = __hadd2(__hmul2(k23, h23), b23);

    float2 f01 = __half22float2(r01);
    float2 f23 = __half22float2(r23);
    return make_float4(f01.x, f01.y, f23.x, f23.y);
}

__global__ __launch_bounds__(256)
void lut_silu_kernel(const float4* __restrict__ x,
                     const void* __restrict__ tA,
                     const void* __restrict__ tB,
                     float4* __restrict__ out,
                     int n4)
{
    __shared__ __half2 lut[1024];

    int mode = g_mode;
    const void* kp = (mode & 1) ? tB : tA;
    const void* bp = (mode & 1) ? tA : tB;
    int dt = mode >> 1;

    for (int i = threadIdx.x; i < 1024; i += blockDim.x) {
        __half kh, bh;
        if (dt == 1) {
            kh = __float2half(((const float*)kp)[i]);
            bh = __float2half(((const float*)bp)[i]);
        } else if (dt == 2) {
            kh = __float2half(__bfloat162float(((const __nv_bfloat16*)kp)[i]));
            bh = __float2half(__bfloat162float(((const __nv_bfloat16*)bp)[i]));
        } else {
            kh = ((const __half*)kp)[i];
            bh = ((const __half*)bp)[i];
        }
        lut[i] = __halves2half2(kh, bh);
    }
    __syncthreads();

    // 8 elements (2x float4) per thread, both loads front-batched for MLP.
    int base = blockIdx.x * (blockDim.x * 2) + threadIdx.x;
    int i0 = base;
    int i1 = base + blockDim.x;

    bool p0 = i0 < n4;
    bool p1 = i1 < n4;
    float4 v0, v1;
    if (p0) v0 = x[i0];
    if (p1) v1 = x[i1];

    if (p0) out[i0] = proc4(v0, lut);
    if (p1) out[i1] = proc4(v1, lut);
}

extern "C" void kernel_launch(void* const* d_in, const int* in_sizes, int n_in,
                              void* d_out, int out_size)
{
    // x = the large input; the other two are the 1024-entry tables.
    int xi = 0;
    for (int i = 1; i < n_in; i++)
        if (in_sizes[i] > in_sizes[xi]) xi = i;

    const void* tabs[2];
    int t = 0;
    for (int i = 0; i < n_in && t < 2; i++)
        if (i != xi) tabs[t++] = d_in[i];

    const float* x = (const float*)d_in[xi];
    float* out = (float*)d_out;

    int n  = in_sizes[xi];
    int n4 = n >> 2;

    sniff_kernel<<<1, 1>>>((const unsigned*)tabs[0], (const unsigned*)tabs[1]);

    int threads = 256;
    int elemsPerBlock = threads * 2;          // 2 float4 per thread
    int blocks = (n4 + elemsPerBlock - 1) / elemsPerBlock;
    lut_silu_kernel<<<blocks, threads>>>(
        (const float4*)x, tabs[0], tabs[1], (float4*)out, n4);
}